// round 16
// baseline (speedup 1.0000x reference)
#include <cuda_runtime.h>
#include <cuda_bf16.h>
#include <math.h>
#include <stdint.h>

#define E      1024
#define INNER  2048
#define NHQ    512
#define NH     4
#define DH     512
#define CK     4
#define S      46
#define B      64
#define OUT    512
#define NB     8
#define BS     (B*S)
#define TG     16

// ---------------- static scratch (no allocations allowed) ----------------
__device__ float d_x[BS * E];
__device__ float d_up[BS * 2 * INNER];
__device__ float d_xact[BS * INNER];
__device__ float d_gatein[BS * 3 * INNER];
__device__ float d_ipre[B * NH * S];
__device__ float d_fpre[B * NH * S];
__device__ float d_last[B * E];

__device__ __nv_bfloat16 d_xlnhi[BS * E];
__device__ __nv_bfloat16 d_xlnlo[BS * E];
__device__ __nv_bfloat16 d_hhi[BS * INNER];
__device__ __nv_bfloat16 d_hlo[BS * INNER];
__device__ __nv_bfloat16 d_wuphi[NB * E * 2 * INNER];
__device__ __nv_bfloat16 d_wuplo[NB * E * 2 * INNER];
__device__ __nv_bfloat16 d_wdnhi[NB * INNER * E];
__device__ __nv_bfloat16 d_wdnlo[NB * INNER * E];

// ---------------- helpers ----------------
__device__ __forceinline__ uint32_t smem_u32(const void* p) {
    return (uint32_t)__cvta_generic_to_shared(p);
}
__device__ __forceinline__ void ldsm4(uint32_t& r0, uint32_t& r1, uint32_t& r2, uint32_t& r3, uint32_t addr) {
    asm volatile("ldmatrix.sync.aligned.m8n8.x4.shared.b16 {%0,%1,%2,%3}, [%4];"
                 : "=r"(r0), "=r"(r1), "=r"(r2), "=r"(r3) : "r"(addr));
}
__device__ __forceinline__ void ldsm4t(uint32_t& r0, uint32_t& r1, uint32_t& r2, uint32_t& r3, uint32_t addr) {
    asm volatile("ldmatrix.sync.aligned.m8n8.x4.trans.shared.b16 {%0,%1,%2,%3}, [%4];"
                 : "=r"(r0), "=r"(r1), "=r"(r2), "=r"(r3) : "r"(addr));
}
__device__ __forceinline__ void mma16816(float* d, const uint32_t* a, const uint32_t* b) {
    asm volatile("mma.sync.aligned.m16n8k16.row.col.f32.bf16.bf16.f32 "
                 "{%0,%1,%2,%3}, {%4,%5,%6,%7}, {%8,%9}, {%0,%1,%2,%3};"
                 : "+f"(d[0]), "+f"(d[1]), "+f"(d[2]), "+f"(d[3])
                 : "r"(a[0]), "r"(a[1]), "r"(a[2]), "r"(a[3]), "r"(b[0]), "r"(b[1]));
}
__device__ __forceinline__ void cpa16(uint32_t sdst, const void* gsrc) {
    asm volatile("cp.async.cg.shared.global [%0], [%1], 16;"
                 :: "r"(sdst), "l"(gsrc));
}
__device__ __forceinline__ void split1(float x, __nv_bfloat16& h, __nv_bfloat16& l) {
    h = __float2bfloat16_rn(x);
    l = __float2bfloat16_rn(x - __bfloat162float(h));
}

// ---------------- fp32 -> (hi,lo) bf16 split ----------------
__global__ __launch_bounds__(256) void split_kernel(
    const float* __restrict__ src, __nv_bfloat16* __restrict__ hi,
    __nv_bfloat16* __restrict__ lo, size_t n)
{
    size_t i = ((size_t)blockIdx.x * 256 + threadIdx.x) * 4;
    if (i >= n) return;
    float4 v = *(const float4*)(src + i);
    __nv_bfloat16 h0, h1, h2, h3, l0, l1, l2, l3;
    split1(v.x, h0, l0); split1(v.y, h1, l1);
    split1(v.z, h2, l2); split1(v.w, h3, l3);
    *(__nv_bfloat162*)(hi + i)     = __nv_bfloat162(h0, h1);
    *(__nv_bfloat162*)(hi + i + 2) = __nv_bfloat162(h2, h3);
    *(__nv_bfloat162*)(lo + i)     = __nv_bfloat162(l0, l1);
    *(__nv_bfloat162*)(lo + i + 2) = __nv_bfloat162(l2, l3);
}

// ---------------- LayerNorm ----------------
template<int SPLIT>
__global__ __launch_bounds__(256) void ln_kernel(
    const float* __restrict__ in, size_t in_stride,
    const float* __restrict__ w,
    float* __restrict__ outf,
    __nv_bfloat16* __restrict__ oh, __nv_bfloat16* __restrict__ ol,
    size_t out_stride)
{
    int row = blockIdx.x;
    const float* x = in + (size_t)row * in_stride;
    int tid = threadIdx.x;
    float s = 0.f, ss = 0.f;
    for (int i = tid; i < E; i += 256) { float v = x[i]; s += v; ss += v * v; }
    __shared__ float r1[256], r2[256];
    r1[tid] = s; r2[tid] = ss;
    __syncthreads();
    for (int st = 128; st > 0; st >>= 1) {
        if (tid < st) { r1[tid] += r1[tid + st]; r2[tid] += r2[tid + st]; }
        __syncthreads();
    }
    float mean = r1[0] * (1.f / E);
    float var  = r2[0] * (1.f / E) - mean * mean;
    float inv  = rsqrtf(var + 1e-5f);
    for (int i = tid; i < E; i += 256) {
        float v = (x[i] - mean) * inv * w[i];
        if (SPLIT) {
            __nv_bfloat16 h, l;
            split1(v, h, l);
            oh[(size_t)row * out_stride + i] = h;
            ol[(size_t)row * out_stride + i] = l;
        } else {
            outf[(size_t)row * out_stride + i] = v;
        }
    }
}

// ---------------- split-bf16 GEMM: 3-stage cp.async, swizzled smem ----------------
// ADD: 0=store, 1=load-add-store, 2=atomicAdd (for split-K; C must be pre-zeroed)
// Kd = K length per z-split; Ktot = full row stride of A.
template<int ADD, int MT, int NT>
__global__ __launch_bounds__(256, 2) void gemm_kernel(
    const __nv_bfloat16* __restrict__ Ahg, const __nv_bfloat16* __restrict__ Alg,
    const __nv_bfloat16* __restrict__ Bhg, const __nv_bfloat16* __restrict__ Blg,
    float* __restrict__ C, int M, int N, int Kd, int Ktot)
{
    constexpr uint32_t ATILE = (uint32_t)MT * 64u;
    constexpr int BU = NT / 8;
    constexpr uint32_t BROWB = NT * 2;
    constexpr uint32_t BTILE = 32u * NT * 2u;
    constexpr uint32_t STG = 2u * ATILE + 2u * BTILE;
    constexpr uint32_t OAL = ATILE, OBH = 2u * ATILE, OBL = 2u * ATILE + BTILE;
    constexpr int NGRP = NT / 32;
    constexpr int MTW  = MT / 64;
    constexpr int ACH  = (MT * 4) / 256;
    constexpr int BCH  = (NT * 4) / 256;

    extern __shared__ char smraw[];
    uint32_t sb = (smem_u32(smraw) + 1023u) & ~1023u;

    int tid  = threadIdx.x;
    int lane = tid & 31, warp = tid >> 5;
    int bm = blockIdx.y * MT, bn = blockIdx.x * NT;
    size_t koff = (size_t)blockIdx.z * Kd;
    int wm = (warp >> 1) * (MT / 4);
    int wn = (warp & 1) * (NT / 2);

    int a_r0 = tid >> 2,           a_u0 = tid & 3;
    uint32_t a_off0 = ((uint32_t)a_r0 << 6) + (((uint32_t)(a_u0 ^ ((a_r0 >> 1) & 3))) << 4);
    size_t ag0 = (size_t)(bm + a_r0) * Ktot + koff + a_u0 * 8;
    int a_r1 = (tid + 256) >> 2,   a_u1 = tid & 3;
    uint32_t a_off1 = ((uint32_t)a_r1 << 6) + (((uint32_t)(a_u1 ^ ((a_r1 >> 1) & 3))) << 4);
    size_t ag1 = (size_t)(bm + a_r1) * Ktot + koff + a_u1 * 8;

    int b_r0 = tid / BU,           b_u0 = tid % BU;
    uint32_t b_off0 = (uint32_t)b_r0 * BROWB + (((uint32_t)(b_u0 ^ (b_r0 & 7))) << 4);
    size_t bg0 = (koff + b_r0) * N + bn + b_u0 * 8;
    int b_r1 = (tid + 256) / BU,   b_u1 = tid % BU;
    uint32_t b_off1 = (uint32_t)b_r1 * BROWB + (((uint32_t)(b_u1 ^ (b_r1 & 7))) << 4);
    size_t bg1 = (koff + b_r1) * N + bn + b_u1 * 8;

    int a_row_l = lane & 15, a_hi_l = lane >> 4;
    int b_row_l = (lane & 7) + ((lane >> 3) & 1) * 8;
    int b_hi_l  = lane >> 4;

    float acc[MTW][2 * NGRP][4];
    #pragma unroll
    for (int i = 0; i < MTW; i++)
        #pragma unroll
        for (int j = 0; j < 2 * NGRP; j++)
            #pragma unroll
            for (int q = 0; q < 4; q++) acc[i][j][q] = 0.f;

    int ntiles = Kd >> 5;

    auto issue = [&](int kt) {
        uint32_t base = sb + (uint32_t)(kt % 3) * STG;
        int k0 = kt * 32;
        cpa16(base + a_off0,       Ahg + ag0 + k0);
        cpa16(base + OAL + a_off0, Alg + ag0 + k0);
        if (ACH == 2) {
            cpa16(base + a_off1,       Ahg + ag1 + k0);
            cpa16(base + OAL + a_off1, Alg + ag1 + k0);
        }
        cpa16(base + OBH + b_off0, Bhg + bg0 + (size_t)k0 * N);
        cpa16(base + OBL + b_off0, Blg + bg0 + (size_t)k0 * N);
        if (BCH == 2) {
            cpa16(base + OBH + b_off1, Bhg + bg1 + (size_t)k0 * N);
            cpa16(base + OBL + b_off1, Blg + bg1 + (size_t)k0 * N);
        }
        asm volatile("cp.async.commit_group;");
    };

    issue(0);
    if (ntiles > 1) issue(1);

    for (int kt = 0; kt < ntiles; kt++) {
        if (kt + 1 < ntiles) asm volatile("cp.async.wait_group 1;");
        else                 asm volatile("cp.async.wait_group 0;");
        __syncthreads();
        if (kt + 2 < ntiles) issue(kt + 2);

        uint32_t base = sb + (uint32_t)(kt % 3) * STG;

        #pragma unroll
        for (int h = 0; h < 2; h++) {
            uint32_t rah[MTW][4], ral[MTW][4];
            int a_u = h * 2 + a_hi_l;
            #pragma unroll
            for (int mt = 0; mt < MTW; mt++) {
                int row = wm + mt * 16 + a_row_l;
                uint32_t ao = ((uint32_t)row << 6)
                            + (((uint32_t)(a_u ^ ((row >> 1) & 3))) << 4);
                ldsm4(rah[mt][0], rah[mt][1], rah[mt][2], rah[mt][3], base + ao);
                ldsm4(ral[mt][0], ral[mt][1], ral[mt][2], ral[mt][3], base + OAL + ao);
            }
            int brow = h * 16 + b_row_l;
            uint32_t brsw = (uint32_t)(brow & 7);
            uint32_t bro = (uint32_t)brow * BROWB;
            #pragma unroll
            for (int ng = 0; ng < NGRP; ng++) {
                int b_u = (wn >> 3) + ng * 2 + b_hi_l;
                uint32_t bo = bro + (((uint32_t)b_u ^ brsw) << 4);
                uint32_t rbh[4], rbl[4];
                ldsm4t(rbh[0], rbh[1], rbh[2], rbh[3], base + OBH + bo);
                ldsm4t(rbl[0], rbl[1], rbl[2], rbl[3], base + OBL + bo);
                #pragma unroll
                for (int mt = 0; mt < MTW; mt++) {
                    #pragma unroll
                    for (int nn = 0; nn < 2; nn++) {
                        float* d = acc[mt][ng * 2 + nn];
                        mma16816(d, rah[mt], &rbh[nn * 2]);
                        mma16816(d, rah[mt], &rbl[nn * 2]);
                        mma16816(d, ral[mt], &rbh[nn * 2]);
                    }
                }
            }
        }
    }

    int g = lane >> 2, t2 = (lane & 3) * 2;
    #pragma unroll
    for (int mt = 0; mt < MTW; mt++) {
        #pragma unroll
        for (int nt = 0; nt < 2 * NGRP; nt++) {
            int row = bm + wm + mt * 16 + g;
            int col = bn + wn + nt * 8 + t2;
            float* d = acc[mt][nt];
            float* p0 = &C[(size_t)row * N + col];
            float* p1 = &C[(size_t)(row + 8) * N + col];
            if (ADD == 2) {
                atomicAdd(p0,     d[0]);
                atomicAdd(p0 + 1, d[1]);
                atomicAdd(p1,     d[2]);
                atomicAdd(p1 + 1, d[3]);
            } else if (ADD == 1) {
                float2 o0 = *(float2*)p0, o1 = *(float2*)p1;
                *(float2*)p0 = make_float2(o0.x + d[0], o0.y + d[1]);
                *(float2*)p1 = make_float2(o1.x + d[2], o1.y + d[3]);
            } else {
                *(float2*)p0 = make_float2(d[0], d[1]);
                *(float2*)p1 = make_float2(d[2], d[3]);
            }
        }
    }
}

#define GEMM_SMEM_UP (3 * (2 * 128 * 64 + 2 * 32 * 128 * 2) + 1024)
#define GEMM_SMEM_DN (3 * (2 * 64 * 64 + 2 * 32 * 64 * 2) + 1024)

// ---------------- fused causal dwconv + SiLU + headwise q/k/v ----------------
#define CH_SX   (4 * 64 * 53)
#define CH_SW   (64 * 69)
#define CH_SMEM ((CH_SX + CH_SW) * 4)

__global__ __launch_bounds__(256) void conv_head_kernel(
    const float* __restrict__ cw, const float* __restrict__ cb,
    const float* __restrict__ wq, const float* __restrict__ wk,
    const float* __restrict__ wv)
{
    extern __shared__ float cs[];
    float* sx = cs;
    float* sw = cs + CH_SX;
    int hq0 = blockIdx.x * 64;
    int b   = blockIdx.y;
    int tid = threadIdx.x, warp = tid >> 5, lane = tid & 31;

    for (int i = tid; i < 4 * 64 * 3; i += 256) {
        int ch2 = i / 3, sp = i - ch2 * 3;
        sx[ch2 * 53 + sp] = 0.f;
    }
    for (int i = tid; i < S * 256; i += 256) {
        int s = i >> 8, c = i & 255;
        int j = c & 3, hql = c >> 2;
        sx[(j * 64 + hql) * 53 + 3 + s] =
            d_up[((size_t)(b * S + s)) * 2 * INNER + hq0 * 4 + c];
    }
    for (int i = tid; i < 64 * 68; i += 256) {
        int hql = i / 68, w = i - hql * 68;
        int hg = hq0 + hql;
        float v;
        if (w < 16)      v = cw[hg * 16 + w];
        else if (w < 20) v = cb[hg * 4 + (w - 16)];
        else if (w < 36) v = wq[hg * 16 + (w - 20)];
        else if (w < 52) v = wk[hg * 16 + (w - 36)];
        else             v = wv[hg * 16 + (w - 52)];
        sw[hql * 69 + w] = v;
    }
    __syncthreads();

    for (int hqi = lane; hqi < 64; hqi += 32) {
        float W[68];
        #pragma unroll
        for (int w = 0; w < 68; w++) W[w] = sw[hqi * 69 + w];
        for (int s = warp; s < S; s += 8) {
            size_t row = (size_t)b * S + s;
            float a[4], xi[4];
            #pragma unroll
            for (int j = 0; j < 4; j++) {
                const float* xp = &sx[(j * 64 + hqi) * 53 + s];
                float o = W[j*4+0]*xp[0] + W[j*4+1]*xp[1]
                        + W[j*4+2]*xp[2] + W[j*4+3]*xp[3] + W[16+j];
                a[j]  = o / (1.f + expf(-o));
                xi[j] = xp[3];
            }
            *(float4*)(d_xact + row * INNER + (hq0 + hqi) * 4) = *(float4*)a;
            float qo[4], ko[4], vo[4];
            #pragma unroll
            for (int o = 0; o < 4; o++) {
                float sq = 0.f, sk = 0.f, sv = 0.f;
                #pragma unroll
                for (int d = 0; d < 4; d++) {
                    sq += W[20 + o*4 + d] * a[d];
                    sk += W[36 + o*4 + d] * a[d];
                    sv += W[52 + o*4 + d] * xi[d];
                }
                qo[o] = sq; ko[o] = sk; vo[o] = sv;
            }
            float* gp = d_gatein + row * 3 * INNER;
            *(float4*)(gp + (hq0 + hqi) * 4)             = *(float4*)qo;
            *(float4*)(gp + INNER + (hq0 + hqi) * 4)     = *(float4*)ko;
            *(float4*)(gp + 2 * INNER + (hq0 + hqi) * 4) = *(float4*)vo;
        }
    }
}

// ---------------- gate pre-activations: 8 rows/block, smem-staged weights ----------------
__global__ __launch_bounds__(256) void gate_kernel(
    const float* __restrict__ igw, const float* __restrict__ igb,
    const float* __restrict__ fgw, const float* __restrict__ fgb)
{
    __shared__ float sw[1024][9];
    int tid = threadIdx.x, warp = tid >> 5, lane = tid & 31;
    int row = blockIdx.x * 8 + warp;
    int b = row / S, s = row - b * S;
    const float* g = d_gatein + (size_t)row * 3 * INNER;
    float acc[8] = {0.f,0.f,0.f,0.f,0.f,0.f,0.f,0.f};

    for (int k0 = 0; k0 < 3 * INNER; k0 += 1024) {
        if (k0) __syncthreads();
        for (int i = tid; i < 1024; i += 256) {
            float4 a = *(const float4*)(igw + (size_t)(k0 + i) * NH);
            float4 f = *(const float4*)(fgw + (size_t)(k0 + i) * NH);
            sw[i][0] = a.x; sw[i][1] = a.y; sw[i][2] = a.z; sw[i][3] = a.w;
            sw[i][4] = f.x; sw[i][5] = f.y; sw[i][6] = f.z; sw[i][7] = f.w;
        }
        __syncthreads();
        #pragma unroll 4
        for (int kk = lane; kk < 1024; kk += 32) {
            float gv = g[k0 + kk];
            #pragma unroll
            for (int j = 0; j < 8; j++) acc[j] += gv * sw[kk][j];
        }
    }
    #pragma unroll
    for (int off = 16; off; off >>= 1)
        #pragma unroll
        for (int j = 0; j < 8; j++)
            acc[j] += __shfl_down_sync(0xffffffffu, acc[j], off);
    if (lane == 0) {
        #pragma unroll
        for (int j = 0; j < 4; j++) {
            d_ipre[(b * NH + j) * S + s] = acc[j] + igb[j];
            d_fpre[(b * NH + j) * S + s] = acc[j + 4] + fgb[j];
        }
    }
}

// ---------------- mLSTM (TG=16) + fused per-head norm/skip/z-gate -> split bf16 ----------------
__global__ __launch_bounds__(256) void mlstm_kernel(
    const float* __restrict__ mhw, const float* __restrict__ skipw)
{
    int tg = blockIdx.x;
    int bh = blockIdx.y;
    int b = bh >> 2, hh = bh & 3;
    int t0 = tg * TG;
    int nt = (t0 + TG <= S) ? TG : (S - t0);
    int maxs = t0 + nt;
    int tid = threadIdx.x, warp = tid >> 5, lane = tid & 31;

    __shared__ float qs[TG][DH];
    __shared__ float cums[S], ips[S], lsig[S];
    __shared__ float coeff[TG][64];
    __shared__ float rsum[TG][8], rsq[TG][8];
    __shared__ float smean[TG], sinv[TG];

    const float* gbase = d_gatein + (size_t)b * S * 3 * INNER;

    for (int i = tid; i < nt * DH; i += 256) {
        int tt = i >> 9, j = i & (DH - 1);
        qs[tt][j] = gbase[(size_t)(t0 + tt) * 3 * INNER + hh * DH + j];
    }
    if (tid < S) {
        ips[tid] = d_ipre[bh * S + tid];
        float x = d_fpre[bh * S + tid];
        lsig[tid] = (x < 0.f) ? (x - log1pf(expf(x))) : (-log1pf(expf(-x)));
    }
    __syncthreads();

    for (int s = warp; s < maxs; s += 8) {
        const float* krow = gbase + (size_t)s * 3 * INNER + INNER + hh * DH;
        float kv[16];
        #pragma unroll
        for (int j = 0; j < 16; j++) kv[j] = krow[lane + j * 32];
        #pragma unroll
        for (int tt = 0; tt < TG; tt++) {
            float p = 0.f;
            #pragma unroll
            for (int j = 0; j < 16; j++) p += qs[tt][lane + j * 32] * kv[j];
            #pragma unroll
            for (int off = 16; off; off >>= 1)
                p += __shfl_down_sync(0xffffffffu, p, off);
            if (lane == 0) coeff[tt][s] = p;
        }
    }
    __syncthreads();

    if (tid == 0) {
        float a = 0.f;
        for (int s = 0; s < S; s++) { a += lsig[s]; cums[s] = a; }
    }
    __syncthreads();

    for (int tt = warp; tt < nt; tt += 8) {
        int t = t0 + tt;
        float ct = cums[t];
        int s1 = lane, s2 = lane + 32;
        float ld1 = (s1 <= t) ? (ct - cums[s1] + ips[s1]) : -INFINITY;
        float ld2 = (s2 <= t) ? (ct - cums[s2] + ips[s2]) : -INFINITY;
        float m = fmaxf(ld1, ld2);
        #pragma unroll
        for (int off = 16; off; off >>= 1)
            m = fmaxf(m, __shfl_xor_sync(0xffffffffu, m, off));
        const float scale = 0.04419417382f;
        float cv1 = (s1 <= t) ? coeff[tt][s1] * scale * expf(ld1 - m) : 0.f;
        float cv2 = (s2 <= t) ? coeff[tt][s2] * scale * expf(ld2 - m) : 0.f;
        float cs = cv1 + cv2;
        #pragma unroll
        for (int off = 16; off; off >>= 1)
            cs += __shfl_xor_sync(0xffffffffu, cs, off);
        float denom = fmaxf(fabsf(cs), expf(-m)) + 1e-6f;
        float inv = 1.f / denom;
        coeff[tt][s1] = cv1 * inv;
        coeff[tt][s2] = cv2 * inv;
    }
    __syncthreads();

    int d0 = tid, d1 = tid + 256;
    float a0[TG], a1[TG];
    #pragma unroll
    for (int tt = 0; tt < TG; tt++) { a0[tt] = 0.f; a1[tt] = 0.f; }
    for (int s = 0; s < maxs; s++) {
        const float* vrow = gbase + (size_t)s * 3 * INNER + 2 * INNER + hh * DH;
        float v0 = vrow[d0], v1 = vrow[d1];
        #pragma unroll
        for (int tt = 0; tt < TG; tt++) {
            float c = coeff[tt][s];
            a0[tt] += c * v0;
            a1[tt] += c * v1;
        }
    }

    #pragma unroll
    for (int tt = 0; tt < TG; tt++) {
        float v = a0[tt] + a1[tt];
        float q = a0[tt] * a0[tt] + a1[tt] * a1[tt];
        #pragma unroll
        for (int off = 16; off; off >>= 1) {
            v += __shfl_down_sync(0xffffffffu, v, off);
            q += __shfl_down_sync(0xffffffffu, q, off);
        }
        if (lane == 0) { rsum[tt][warp] = v; rsq[tt][warp] = q; }
    }
    __syncthreads();
    if (tid < TG) {
        float v = 0.f, q = 0.f;
        #pragma unroll
        for (int w = 0; w < 8; w++) { v += rsum[tid][w]; q += rsq[tid][w]; }
        float mean = v * (1.f / DH);
        float var  = q * (1.f / DH) - mean * mean;
        smean[tid] = mean;
        sinv[tid]  = rsqrtf(var + 1e-5f);
    }
    __syncthreads();

    int c0 = hh * DH + tid, c1 = c0 + 256;
    float mh0 = mhw[c0], mh1 = mhw[c1];
    float sk0 = skipw[c0], sk1 = skipw[c1];
    for (int tt = 0; tt < nt; tt++) {
        size_t row = (size_t)(b * S + t0 + tt);
        float mean = smean[tt], inv = sinv[tt];
        float z0 = d_up[row * 2 * INNER + INNER + c0];
        float z1 = d_up[row * 2 * INNER + INNER + c1];
        float sz0 = z0 / (1.f + expf(-z0));
        float sz1 = z1 / (1.f + expf(-z1));
        float xa0 = d_xact[row * INNER + c0];
        float xa1 = d_xact[row * INNER + c1];
        float val0 = ((a0[tt] - mean) * inv * mh0 + sk0 * xa0) * sz0;
        float val1 = ((a1[tt] - mean) * inv * mh1 + sk1 * xa1) * sz1;
        __nv_bfloat16 h, l;
        split1(val0, h, l);
        d_hhi[row * INNER + c0] = h;
        d_hlo[row * INNER + c0] = l;
        split1(val1, h, l);
        d_hhi[row * INNER + c1] = h;
        d_hlo[row * INNER + c1] = l;
    }
}

// ---------------- final projection ----------------
__global__ void proj_kernel(const float* __restrict__ pw,
                            const float* __restrict__ pb,
                            float* __restrict__ out)
{
    int o = blockIdx.x * blockDim.x + threadIdx.x;
    int b = blockIdx.y;
    const float* l = d_last + (size_t)b * E;
    float acc = pb[o];
    for (int e = 0; e < E; e++) acc += l[e] * pw[(size_t)e * OUT + o];
    out[b * OUT + o] = acc;
}

// ---------------- host launcher ----------------
extern "C" void kernel_launch(void* const* d_in, const int* in_sizes, int n_in,
                              void* d_out, int out_size)
{
    const float* in_x      = (const float*)d_in[0];
    const float* ln_w      = (const float*)d_in[1];
    const float* w_up      = (const float*)d_in[2];
    const float* conv_w    = (const float*)d_in[3];
    const float* conv_b    = (const float*)d_in[4];
    const float* wq        = (const float*)d_in[5];
    const float* wk        = (const float*)d_in[6];
    const float* wv        = (const float*)d_in[7];
    const float* ig_w      = (const float*)d_in[8];
    const float* ig_b      = (const float*)d_in[9];
    const float* fg_w      = (const float*)d_in[10];
    const float* fg_b      = (const float*)d_in[11];
    const float* skip      = (const float*)d_in[12];
    const float* mhn_w     = (const float*)d_in[13];
    const float* w_down    = (const float*)d_in[14];
    const float* post_ln_w = (const float*)d_in[15];
    const float* proj_w    = (const float*)d_in[16];
    const float* proj_b    = (const float*)d_in[17];
    float* out = (float*)d_out;

    float *px, *pup, *plast;
    __nv_bfloat16 *pxh, *pxl, *phh, *phl, *puh, *pul, *pdh, *pdl;
    cudaGetSymbolAddress((void**)&px,    d_x);
    cudaGetSymbolAddress((void**)&pup,   d_up);
    cudaGetSymbolAddress((void**)&plast, d_last);
    cudaGetSymbolAddress((void**)&pxh,   d_xlnhi);
    cudaGetSymbolAddress((void**)&pxl,   d_xlnlo);
    cudaGetSymbolAddress((void**)&phh,   d_hhi);
    cudaGetSymbolAddress((void**)&phl,   d_hlo);
    cudaGetSymbolAddress((void**)&puh,   d_wuphi);
    cudaGetSymbolAddress((void**)&pul,   d_wuplo);
    cudaGetSymbolAddress((void**)&pdh,   d_wdnhi);
    cudaGetSymbolAddress((void**)&pdl,   d_wdnlo);

    static bool attr_set = false;
    if (!attr_set) {
        cudaFuncSetAttribute((const void*)gemm_kernel<2, 128, 128>,
            cudaFuncAttributeMaxDynamicSharedMemorySize, GEMM_SMEM_UP);
        cudaFuncSetAttribute((const void*)gemm_kernel<1, 64, 64>,
            cudaFuncAttributeMaxDynamicSharedMemorySize, GEMM_SMEM_DN);
        cudaFuncSetAttribute((const void*)conv_head_kernel,
            cudaFuncAttributeMaxDynamicSharedMemorySize, CH_SMEM);
        attr_set = true;
    }

    cudaMemcpyAsync(px, in_x, sizeof(float) * (size_t)BS * E,
                    cudaMemcpyDeviceToDevice);

    {
        size_t nu = (size_t)NB * E * 2 * INNER;
        split_kernel<<<(unsigned)(nu / 4 / 256), 256>>>(w_up, puh, pul, nu);
        size_t nd = (size_t)NB * INNER * E;
        split_kernel<<<(unsigned)(nd / 4 / 256), 256>>>(w_down, pdh, pdl, nd);
    }

    for (int bi = 0; bi < NB; bi++) {
        ln_kernel<1><<<BS, 256>>>(px, E, ln_w + (size_t)bi * E,
                                  nullptr, pxh, pxl, E);

        // split-K=2 up-GEMM with deterministic atomic accumulation
        cudaMemsetAsync(pup, 0, sizeof(float) * (size_t)BS * 2 * INNER);
        dim3 gu(2 * INNER / 128, BS / 128, 2);
        gemm_kernel<2, 128, 128><<<gu, 256, GEMM_SMEM_UP>>>(pxh, pxl,
                                    puh + (size_t)bi * E * 2 * INNER,
                                    pul + (size_t)bi * E * 2 * INNER,
                                    pup, BS, 2 * INNER, E / 2, E);

        conv_head_kernel<<<dim3(NHQ / 64, B), 256, CH_SMEM>>>(
            conv_w + (size_t)bi * INNER * CK, conv_b + (size_t)bi * INNER,
            wq + (size_t)bi * NHQ * 16, wk + (size_t)bi * NHQ * 16,
            wv + (size_t)bi * NHQ * 16);

        gate_kernel<<<BS / 8, 256>>>(
            ig_w + (size_t)bi * 3 * INNER * NH, ig_b + (size_t)bi * NH,
            fg_w + (size_t)bi * 3 * INNER * NH, fg_b + (size_t)bi * NH);

        mlstm_kernel<<<dim3((S + TG - 1) / TG, B * NH), 256>>>(
            mhn_w + (size_t)bi * INNER, skip + (size_t)bi * INNER);

        dim3 gd(E / 64, BS / 64, 1);
        gemm_kernel<1, 64, 64><<<gd, 256, GEMM_SMEM_DN>>>(phh, phl,
                                    pdh + (size_t)bi * INNER * E,
                                    pdl + (size_t)bi * INNER * E,
                                    px, BS, E, INNER, INNER);
    }

    ln_kernel<0><<<B, 256>>>(px + (size_t)(S - 1) * E, (size_t)S * E,
                             post_ln_w, plast, nullptr, nullptr, E);
    proj_kernel<<<dim3(OUT / 256, B), 256>>>(proj_w, proj_b, out);
}

// round 17
// speedup vs baseline: 1.0485x; 1.0485x over previous
#include <cuda_runtime.h>
#include <cuda_bf16.h>
#include <math.h>
#include <stdint.h>

#define E      1024
#define INNER  2048
#define NHQ    512
#define NH     4
#define DH     512
#define CK     4
#define S      46
#define B      64
#define OUT    512
#define NB     8
#define BS     (B*S)
#define TG     16

// ---------------- static scratch (no allocations allowed) ----------------
__device__ float d_x[BS * E];
__device__ float d_up[BS * 2 * INNER];
__device__ float d_xact[BS * INNER];
__device__ float d_gatein[BS * 3 * INNER];
__device__ float d_ipre[B * NH * S];
__device__ float d_fpre[B * NH * S];
__device__ float d_last[B * E];

__device__ __nv_bfloat16 d_xlnhi[BS * E];
__device__ __nv_bfloat16 d_xlnlo[BS * E];
__device__ __nv_bfloat16 d_hhi[BS * INNER];
__device__ __nv_bfloat16 d_hlo[BS * INNER];
__device__ __nv_bfloat16 d_wuphi[NB * E * 2 * INNER];
__device__ __nv_bfloat16 d_wuplo[NB * E * 2 * INNER];
__device__ __nv_bfloat16 d_wdnhi[NB * INNER * E];
__device__ __nv_bfloat16 d_wdnlo[NB * INNER * E];

// ---------------- helpers ----------------
__device__ __forceinline__ uint32_t smem_u32(const void* p) {
    return (uint32_t)__cvta_generic_to_shared(p);
}
__device__ __forceinline__ void ldsm4(uint32_t& r0, uint32_t& r1, uint32_t& r2, uint32_t& r3, uint32_t addr) {
    asm volatile("ldmatrix.sync.aligned.m8n8.x4.shared.b16 {%0,%1,%2,%3}, [%4];"
                 : "=r"(r0), "=r"(r1), "=r"(r2), "=r"(r3) : "r"(addr));
}
__device__ __forceinline__ void ldsm4t(uint32_t& r0, uint32_t& r1, uint32_t& r2, uint32_t& r3, uint32_t addr) {
    asm volatile("ldmatrix.sync.aligned.m8n8.x4.trans.shared.b16 {%0,%1,%2,%3}, [%4];"
                 : "=r"(r0), "=r"(r1), "=r"(r2), "=r"(r3) : "r"(addr));
}
__device__ __forceinline__ void mma16816(float* d, const uint32_t* a, const uint32_t* b) {
    asm volatile("mma.sync.aligned.m16n8k16.row.col.f32.bf16.bf16.f32 "
                 "{%0,%1,%2,%3}, {%4,%5,%6,%7}, {%8,%9}, {%0,%1,%2,%3};"
                 : "+f"(d[0]), "+f"(d[1]), "+f"(d[2]), "+f"(d[3])
                 : "r"(a[0]), "r"(a[1]), "r"(a[2]), "r"(a[3]), "r"(b[0]), "r"(b[1]));
}
__device__ __forceinline__ void cpa16(uint32_t sdst, const void* gsrc) {
    asm volatile("cp.async.cg.shared.global [%0], [%1], 16;"
                 :: "r"(sdst), "l"(gsrc));
}
__device__ __forceinline__ void split1(float x, __nv_bfloat16& h, __nv_bfloat16& l) {
    h = __float2bfloat16_rn(x);
    l = __float2bfloat16_rn(x - __bfloat162float(h));
}

// ---------------- fp32 -> (hi,lo) bf16 split ----------------
__global__ __launch_bounds__(256) void split_kernel(
    const float* __restrict__ src, __nv_bfloat16* __restrict__ hi,
    __nv_bfloat16* __restrict__ lo, size_t n)
{
    size_t i = ((size_t)blockIdx.x * 256 + threadIdx.x) * 4;
    if (i >= n) return;
    float4 v = *(const float4*)(src + i);
    __nv_bfloat16 h0, h1, h2, h3, l0, l1, l2, l3;
    split1(v.x, h0, l0); split1(v.y, h1, l1);
    split1(v.z, h2, l2); split1(v.w, h3, l3);
    *(__nv_bfloat162*)(hi + i)     = __nv_bfloat162(h0, h1);
    *(__nv_bfloat162*)(hi + i + 2) = __nv_bfloat162(h2, h3);
    *(__nv_bfloat162*)(lo + i)     = __nv_bfloat162(l0, l1);
    *(__nv_bfloat162*)(lo + i + 2) = __nv_bfloat162(l2, l3);
}

// ---------------- LayerNorm: single-pass, register-resident row ----------------
// 256 threads x float4 = E=1024 exactly. One global read of x; 2 barriers.
template<int SPLIT>
__global__ __launch_bounds__(256) void ln_kernel(
    const float* __restrict__ in, size_t in_stride,
    const float* __restrict__ w,
    float* __restrict__ outf,
    __nv_bfloat16* __restrict__ oh, __nv_bfloat16* __restrict__ ol,
    size_t out_stride)
{
    int row = blockIdx.x;
    int tid = threadIdx.x, warp = tid >> 5, lane = tid & 31;
    const float* x = in + (size_t)row * in_stride;

    float4 v = *(const float4*)(x + tid * 4);
    float s  = v.x + v.y + v.z + v.w;
    float ss = v.x * v.x + v.y * v.y + v.z * v.z + v.w * v.w;
    #pragma unroll
    for (int off = 16; off; off >>= 1) {
        s  += __shfl_down_sync(0xffffffffu, s, off);
        ss += __shfl_down_sync(0xffffffffu, ss, off);
    }
    __shared__ float wsum[8], wsq[8];
    if (lane == 0) { wsum[warp] = s; wsq[warp] = ss; }
    __syncthreads();
    float ts = 0.f, tq = 0.f;
    #pragma unroll
    for (int i = 0; i < 8; i++) { ts += wsum[i]; tq += wsq[i]; }
    float mean = ts * (1.f / E);
    float var  = tq * (1.f / E) - mean * mean;
    float inv  = rsqrtf(var + 1e-5f);

    float4 wv = *(const float4*)(w + tid * 4);
    float o0 = (v.x - mean) * inv * wv.x;
    float o1 = (v.y - mean) * inv * wv.y;
    float o2 = (v.z - mean) * inv * wv.z;
    float o3 = (v.w - mean) * inv * wv.w;

    if (SPLIT) {
        __nv_bfloat16 h0, h1, h2, h3, l0, l1, l2, l3;
        split1(o0, h0, l0); split1(o1, h1, l1);
        split1(o2, h2, l2); split1(o3, h3, l3);
        size_t base = (size_t)row * out_stride + tid * 4;
        __nv_bfloat162 hp0(h0, h1), hp1(h2, h3), lp0(l0, l1), lp1(l2, l3);
        uint2 hv, lv;
        hv.x = *(uint32_t*)&hp0; hv.y = *(uint32_t*)&hp1;
        lv.x = *(uint32_t*)&lp0; lv.y = *(uint32_t*)&lp1;
        *(uint2*)(oh + base) = hv;
        *(uint2*)(ol + base) = lv;
    } else {
        *(float4*)(outf + (size_t)row * out_stride + tid * 4)
            = make_float4(o0, o1, o2, o3);
    }
}

// ---------------- split-bf16 GEMM: 3-stage cp.async, swizzled smem ----------------
template<int ADD, int MT, int NT>
__global__ __launch_bounds__(256, 2) void gemm_kernel(
    const __nv_bfloat16* __restrict__ Ahg, const __nv_bfloat16* __restrict__ Alg,
    const __nv_bfloat16* __restrict__ Bhg, const __nv_bfloat16* __restrict__ Blg,
    float* __restrict__ C, int M, int N, int Kd)
{
    constexpr uint32_t ATILE = (uint32_t)MT * 64u;
    constexpr int BU = NT / 8;
    constexpr uint32_t BROWB = NT * 2;
    constexpr uint32_t BTILE = 32u * NT * 2u;
    constexpr uint32_t STG = 2u * ATILE + 2u * BTILE;
    constexpr uint32_t OAL = ATILE, OBH = 2u * ATILE, OBL = 2u * ATILE + BTILE;
    constexpr int NGRP = NT / 32;
    constexpr int MTW  = MT / 64;
    constexpr int ACH  = (MT * 4) / 256;
    constexpr int BCH  = (NT * 4) / 256;

    extern __shared__ char smraw[];
    uint32_t sb = (smem_u32(smraw) + 1023u) & ~1023u;

    int tid  = threadIdx.x;
    int lane = tid & 31, warp = tid >> 5;
    int bm = blockIdx.y * MT, bn = blockIdx.x * NT;
    int wm = (warp >> 1) * (MT / 4);
    int wn = (warp & 1) * (NT / 2);

    int a_r0 = tid >> 2,           a_u0 = tid & 3;
    uint32_t a_off0 = ((uint32_t)a_r0 << 6) + (((uint32_t)(a_u0 ^ ((a_r0 >> 1) & 3))) << 4);
    size_t ag0 = (size_t)(bm + a_r0) * Kd + a_u0 * 8;
    int a_r1 = (tid + 256) >> 2,   a_u1 = tid & 3;
    uint32_t a_off1 = ((uint32_t)a_r1 << 6) + (((uint32_t)(a_u1 ^ ((a_r1 >> 1) & 3))) << 4);
    size_t ag1 = (size_t)(bm + a_r1) * Kd + a_u1 * 8;

    int b_r0 = tid / BU,           b_u0 = tid % BU;
    uint32_t b_off0 = (uint32_t)b_r0 * BROWB + (((uint32_t)(b_u0 ^ (b_r0 & 7))) << 4);
    size_t bg0 = (size_t)b_r0 * N + bn + b_u0 * 8;
    int b_r1 = (tid + 256) / BU,   b_u1 = tid % BU;
    uint32_t b_off1 = (uint32_t)b_r1 * BROWB + (((uint32_t)(b_u1 ^ (b_r1 & 7))) << 4);
    size_t bg1 = (size_t)b_r1 * N + bn + b_u1 * 8;

    int a_row_l = lane & 15, a_hi_l = lane >> 4;
    int b_row_l = (lane & 7) + ((lane >> 3) & 1) * 8;
    int b_hi_l  = lane >> 4;

    float acc[MTW][2 * NGRP][4];
    #pragma unroll
    for (int i = 0; i < MTW; i++)
        #pragma unroll
        for (int j = 0; j < 2 * NGRP; j++)
            #pragma unroll
            for (int q = 0; q < 4; q++) acc[i][j][q] = 0.f;

    int ntiles = Kd >> 5;

    auto issue = [&](int kt) {
        uint32_t base = sb + (uint32_t)(kt % 3) * STG;
        int k0 = kt * 32;
        cpa16(base + a_off0,       Ahg + ag0 + k0);
        cpa16(base + OAL + a_off0, Alg + ag0 + k0);
        if (ACH == 2) {
            cpa16(base + a_off1,       Ahg + ag1 + k0);
            cpa16(base + OAL + a_off1, Alg + ag1 + k0);
        }
        cpa16(base + OBH + b_off0, Bhg + bg0 + (size_t)k0 * N);
        cpa16(base + OBL + b_off0, Blg + bg0 + (size_t)k0 * N);
        if (BCH == 2) {
            cpa16(base + OBH + b_off1, Bhg + bg1 + (size_t)k0 * N);
            cpa16(base + OBL + b_off1, Blg + bg1 + (size_t)k0 * N);
        }
        asm volatile("cp.async.commit_group;");
    };

    issue(0);
    if (ntiles > 1) issue(1);

    for (int kt = 0; kt < ntiles; kt++) {
        if (kt + 1 < ntiles) asm volatile("cp.async.wait_group 1;");
        else                 asm volatile("cp.async.wait_group 0;");
        __syncthreads();
        if (kt + 2 < ntiles) issue(kt + 2);

        uint32_t base = sb + (uint32_t)(kt % 3) * STG;

        #pragma unroll
        for (int h = 0; h < 2; h++) {
            uint32_t rah[MTW][4], ral[MTW][4];
            int a_u = h * 2 + a_hi_l;
            #pragma unroll
            for (int mt = 0; mt < MTW; mt++) {
                int row = wm + mt * 16 + a_row_l;
                uint32_t ao = ((uint32_t)row << 6)
                            + (((uint32_t)(a_u ^ ((row >> 1) & 3))) << 4);
                ldsm4(rah[mt][0], rah[mt][1], rah[mt][2], rah[mt][3], base + ao);
                ldsm4(ral[mt][0], ral[mt][1], ral[mt][2], ral[mt][3], base + OAL + ao);
            }
            int brow = h * 16 + b_row_l;
            uint32_t brsw = (uint32_t)(brow & 7);
            uint32_t bro = (uint32_t)brow * BROWB;
            #pragma unroll
            for (int ng = 0; ng < NGRP; ng++) {
                int b_u = (wn >> 3) + ng * 2 + b_hi_l;
                uint32_t bo = bro + (((uint32_t)b_u ^ brsw) << 4);
                uint32_t rbh[4], rbl[4];
                ldsm4t(rbh[0], rbh[1], rbh[2], rbh[3], base + OBH + bo);
                ldsm4t(rbl[0], rbl[1], rbl[2], rbl[3], base + OBL + bo);
                #pragma unroll
                for (int mt = 0; mt < MTW; mt++) {
                    #pragma unroll
                    for (int nn = 0; nn < 2; nn++) {
                        float* d = acc[mt][ng * 2 + nn];
                        mma16816(d, rah[mt], &rbh[nn * 2]);
                        mma16816(d, rah[mt], &rbl[nn * 2]);
                        mma16816(d, ral[mt], &rbh[nn * 2]);
                    }
                }
            }
        }
    }

    int g = lane >> 2, t2 = (lane & 3) * 2;
    #pragma unroll
    for (int mt = 0; mt < MTW; mt++) {
        #pragma unroll
        for (int nt = 0; nt < 2 * NGRP; nt++) {
            int row = bm + wm + mt * 16 + g;
            int col = bn + wn + nt * 8 + t2;
            float* d = acc[mt][nt];
            float2* p0 = (float2*)&C[(size_t)row * N + col];
            float2* p1 = (float2*)&C[(size_t)(row + 8) * N + col];
            float2 v0 = make_float2(d[0], d[1]);
            float2 v1 = make_float2(d[2], d[3]);
            if (ADD) {
                float2 o0 = *p0, o1 = *p1;
                v0.x += o0.x; v0.y += o0.y;
                v1.x += o1.x; v1.y += o1.y;
            }
            *p0 = v0; *p1 = v1;
        }
    }
}

#define GEMM_SMEM_UP (3 * (2 * 128 * 64 + 2 * 32 * 128 * 2) + 1024)
#define GEMM_SMEM_DN (3 * (2 * 64 * 64 + 2 * 32 * 64 * 2) + 1024)

// ---------------- fused causal dwconv + SiLU + headwise q/k/v ----------------
#define CH_SX   (4 * 64 * 53)
#define CH_SW   (64 * 69)
#define CH_SMEM ((CH_SX + CH_SW) * 4)

__global__ __launch_bounds__(256) void conv_head_kernel(
    const float* __restrict__ cw, const float* __restrict__ cb,
    const float* __restrict__ wq, const float* __restrict__ wk,
    const float* __restrict__ wv)
{
    extern __shared__ float cs[];
    float* sx = cs;
    float* sw = cs + CH_SX;
    int hq0 = blockIdx.x * 64;
    int b   = blockIdx.y;
    int tid = threadIdx.x, warp = tid >> 5, lane = tid & 31;

    for (int i = tid; i < 4 * 64 * 3; i += 256) {
        int ch2 = i / 3, sp = i - ch2 * 3;
        sx[ch2 * 53 + sp] = 0.f;
    }
    for (int i = tid; i < S * 256; i += 256) {
        int s = i >> 8, c = i & 255;
        int j = c & 3, hql = c >> 2;
        sx[(j * 64 + hql) * 53 + 3 + s] =
            d_up[((size_t)(b * S + s)) * 2 * INNER + hq0 * 4 + c];
    }
    for (int i = tid; i < 64 * 68; i += 256) {
        int hql = i / 68, w = i - hql * 68;
        int hg = hq0 + hql;
        float v;
        if (w < 16)      v = cw[hg * 16 + w];
        else if (w < 20) v = cb[hg * 4 + (w - 16)];
        else if (w < 36) v = wq[hg * 16 + (w - 20)];
        else if (w < 52) v = wk[hg * 16 + (w - 36)];
        else             v = wv[hg * 16 + (w - 52)];
        sw[hql * 69 + w] = v;
    }
    __syncthreads();

    for (int hqi = lane; hqi < 64; hqi += 32) {
        float W[68];
        #pragma unroll
        for (int w = 0; w < 68; w++) W[w] = sw[hqi * 69 + w];
        for (int s = warp; s < S; s += 8) {
            size_t row = (size_t)b * S + s;
            float a[4], xi[4];
            #pragma unroll
            for (int j = 0; j < 4; j++) {
                const float* xp = &sx[(j * 64 + hqi) * 53 + s];
                float o = W[j*4+0]*xp[0] + W[j*4+1]*xp[1]
                        + W[j*4+2]*xp[2] + W[j*4+3]*xp[3] + W[16+j];
                a[j]  = o / (1.f + expf(-o));
                xi[j] = xp[3];
            }
            *(float4*)(d_xact + row * INNER + (hq0 + hqi) * 4) = *(float4*)a;
            float qo[4], ko[4], vo[4];
            #pragma unroll
            for (int o = 0; o < 4; o++) {
                float sq = 0.f, sk = 0.f, sv = 0.f;
                #pragma unroll
                for (int d = 0; d < 4; d++) {
                    sq += W[20 + o*4 + d] * a[d];
                    sk += W[36 + o*4 + d] * a[d];
                    sv += W[52 + o*4 + d] * xi[d];
                }
                qo[o] = sq; ko[o] = sk; vo[o] = sv;
            }
            float* gp = d_gatein + row * 3 * INNER;
            *(float4*)(gp + (hq0 + hqi) * 4)             = *(float4*)qo;
            *(float4*)(gp + INNER + (hq0 + hqi) * 4)     = *(float4*)ko;
            *(float4*)(gp + 2 * INNER + (hq0 + hqi) * 4) = *(float4*)vo;
        }
    }
}

// ---------------- gate pre-activations: 8 rows/block, smem-staged weights ----------------
__global__ __launch_bounds__(256) void gate_kernel(
    const float* __restrict__ igw, const float* __restrict__ igb,
    const float* __restrict__ fgw, const float* __restrict__ fgb)
{
    __shared__ float sw[1024][9];
    int tid = threadIdx.x, warp = tid >> 5, lane = tid & 31;
    int row = blockIdx.x * 8 + warp;
    int b = row / S, s = row - b * S;
    const float* g = d_gatein + (size_t)row * 3 * INNER;
    float acc[8] = {0.f,0.f,0.f,0.f,0.f,0.f,0.f,0.f};

    for (int k0 = 0; k0 < 3 * INNER; k0 += 1024) {
        if (k0) __syncthreads();
        for (int i = tid; i < 1024; i += 256) {
            float4 a = *(const float4*)(igw + (size_t)(k0 + i) * NH);
            float4 f = *(const float4*)(fgw + (size_t)(k0 + i) * NH);
            sw[i][0] = a.x; sw[i][1] = a.y; sw[i][2] = a.z; sw[i][3] = a.w;
            sw[i][4] = f.x; sw[i][5] = f.y; sw[i][6] = f.z; sw[i][7] = f.w;
        }
        __syncthreads();
        #pragma unroll 4
        for (int kk = lane; kk < 1024; kk += 32) {
            float gv = g[k0 + kk];
            #pragma unroll
            for (int j = 0; j < 8; j++) acc[j] += gv * sw[kk][j];
        }
    }
    #pragma unroll
    for (int off = 16; off; off >>= 1)
        #pragma unroll
        for (int j = 0; j < 8; j++)
            acc[j] += __shfl_down_sync(0xffffffffu, acc[j], off);
    if (lane == 0) {
        #pragma unroll
        for (int j = 0; j < 4; j++) {
            d_ipre[(b * NH + j) * S + s] = acc[j] + igb[j];
            d_fpre[(b * NH + j) * S + s] = acc[j + 4] + fgb[j];
        }
    }
}

// ---------------- mLSTM (TG=16) + fused per-head norm/skip/z-gate -> split bf16 ----------------
__global__ __launch_bounds__(256) void mlstm_kernel(
    const float* __restrict__ mhw, const float* __restrict__ skipw)
{
    int tg = blockIdx.x;
    int bh = blockIdx.y;
    int b = bh >> 2, hh = bh & 3;
    int t0 = tg * TG;
    int nt = (t0 + TG <= S) ? TG : (S - t0);
    int maxs = t0 + nt;
    int tid = threadIdx.x, warp = tid >> 5, lane = tid & 31;

    __shared__ float qs[TG][DH];
    __shared__ float cums[S], ips[S], lsig[S];
    __shared__ float coeff[TG][64];
    __shared__ float rsum[TG][8], rsq[TG][8];
    __shared__ float smean[TG], sinv[TG];

    const float* gbase = d_gatein + (size_t)b * S * 3 * INNER;

    for (int i = tid; i < nt * DH; i += 256) {
        int tt = i >> 9, j = i & (DH - 1);
        qs[tt][j] = gbase[(size_t)(t0 + tt) * 3 * INNER + hh * DH + j];
    }
    if (tid < S) {
        ips[tid] = d_ipre[bh * S + tid];
        float x = d_fpre[bh * S + tid];
        lsig[tid] = (x < 0.f) ? (x - log1pf(expf(x))) : (-log1pf(expf(-x)));
    }
    __syncthreads();

    for (int s = warp; s < maxs; s += 8) {
        const float* krow = gbase + (size_t)s * 3 * INNER + INNER + hh * DH;
        float kv[16];
        #pragma unroll
        for (int j = 0; j < 16; j++) kv[j] = krow[lane + j * 32];
        #pragma unroll
        for (int tt = 0; tt < TG; tt++) {
            float p = 0.f;
            #pragma unroll
            for (int j = 0; j < 16; j++) p += qs[tt][lane + j * 32] * kv[j];
            #pragma unroll
            for (int off = 16; off; off >>= 1)
                p += __shfl_down_sync(0xffffffffu, p, off);
            if (lane == 0) coeff[tt][s] = p;
        }
    }
    __syncthreads();

    if (tid == 0) {
        float a = 0.f;
        for (int s = 0; s < S; s++) { a += lsig[s]; cums[s] = a; }
    }
    __syncthreads();

    for (int tt = warp; tt < nt; tt += 8) {
        int t = t0 + tt;
        float ct = cums[t];
        int s1 = lane, s2 = lane + 32;
        float ld1 = (s1 <= t) ? (ct - cums[s1] + ips[s1]) : -INFINITY;
        float ld2 = (s2 <= t) ? (ct - cums[s2] + ips[s2]) : -INFINITY;
        float m = fmaxf(ld1, ld2);
        #pragma unroll
        for (int off = 16; off; off >>= 1)
            m = fmaxf(m, __shfl_xor_sync(0xffffffffu, m, off));
        const float scale = 0.04419417382f;
        float cv1 = (s1 <= t) ? coeff[tt][s1] * scale * expf(ld1 - m) : 0.f;
        float cv2 = (s2 <= t) ? coeff[tt][s2] * scale * expf(ld2 - m) : 0.f;
        float cs = cv1 + cv2;
        #pragma unroll
        for (int off = 16; off; off >>= 1)
            cs += __shfl_xor_sync(0xffffffffu, cs, off);
        float denom = fmaxf(fabsf(cs), expf(-m)) + 1e-6f;
        float inv = 1.f / denom;
        coeff[tt][s1] = cv1 * inv;
        coeff[tt][s2] = cv2 * inv;
    }
    __syncthreads();

    int d0 = tid, d1 = tid + 256;
    float a0[TG], a1[TG];
    #pragma unroll
    for (int tt = 0; tt < TG; tt++) { a0[tt] = 0.f; a1[tt] = 0.f; }
    for (int s = 0; s < maxs; s++) {
        const float* vrow = gbase + (size_t)s * 3 * INNER + 2 * INNER + hh * DH;
        float v0 = vrow[d0], v1 = vrow[d1];
        #pragma unroll
        for (int tt = 0; tt < TG; tt++) {
            float c = coeff[tt][s];
            a0[tt] += c * v0;
            a1[tt] += c * v1;
        }
    }

    #pragma unroll
    for (int tt = 0; tt < TG; tt++) {
        float v = a0[tt] + a1[tt];
        float q = a0[tt] * a0[tt] + a1[tt] * a1[tt];
        #pragma unroll
        for (int off = 16; off; off >>= 1) {
            v += __shfl_down_sync(0xffffffffu, v, off);
            q += __shfl_down_sync(0xffffffffu, q, off);
        }
        if (lane == 0) { rsum[tt][warp] = v; rsq[tt][warp] = q; }
    }
    __syncthreads();
    if (tid < TG) {
        float v = 0.f, q = 0.f;
        #pragma unroll
        for (int w = 0; w < 8; w++) { v += rsum[tid][w]; q += rsq[tid][w]; }
        float mean = v * (1.f / DH);
        float var  = q * (1.f / DH) - mean * mean;
        smean[tid] = mean;
        sinv[tid]  = rsqrtf(var + 1e-5f);
    }
    __syncthreads();

    int c0 = hh * DH + tid, c1 = c0 + 256;
    float mh0 = mhw[c0], mh1 = mhw[c1];
    float sk0 = skipw[c0], sk1 = skipw[c1];
    for (int tt = 0; tt < nt; tt++) {
        size_t row = (size_t)(b * S + t0 + tt);
        float mean = smean[tt], inv = sinv[tt];
        float z0 = d_up[row * 2 * INNER + INNER + c0];
        float z1 = d_up[row * 2 * INNER + INNER + c1];
        float sz0 = z0 / (1.f + expf(-z0));
        float sz1 = z1 / (1.f + expf(-z1));
        float xa0 = d_xact[row * INNER + c0];
        float xa1 = d_xact[row * INNER + c1];
        float val0 = ((a0[tt] - mean) * inv * mh0 + sk0 * xa0) * sz0;
        float val1 = ((a1[tt] - mean) * inv * mh1 + sk1 * xa1) * sz1;
        __nv_bfloat16 h, l;
        split1(val0, h, l);
        d_hhi[row * INNER + c0] = h;
        d_hlo[row * INNER + c0] = l;
        split1(val1, h, l);
        d_hhi[row * INNER + c1] = h;
        d_hlo[row * INNER + c1] = l;
    }
}

// ---------------- final projection ----------------
__global__ void proj_kernel(const float* __restrict__ pw,
                            const float* __restrict__ pb,
                            float* __restrict__ out)
{
    int o = blockIdx.x * blockDim.x + threadIdx.x;
    int b = blockIdx.y;
    const float* l = d_last + (size_t)b * E;
    float acc = pb[o];
    for (int e = 0; e < E; e++) acc += l[e] * pw[(size_t)e * OUT + o];
    out[b * OUT + o] = acc;
}

// ---------------- host launcher ----------------
extern "C" void kernel_launch(void* const* d_in, const int* in_sizes, int n_in,
                              void* d_out, int out_size)
{
    const float* in_x      = (const float*)d_in[0];
    const float* ln_w      = (const float*)d_in[1];
    const float* w_up      = (const float*)d_in[2];
    const float* conv_w    = (const float*)d_in[3];
    const float* conv_b    = (const float*)d_in[4];
    const float* wq        = (const float*)d_in[5];
    const float* wk        = (const float*)d_in[6];
    const float* wv        = (const float*)d_in[7];
    const float* ig_w      = (const float*)d_in[8];
    const float* ig_b      = (const float*)d_in[9];
    const float* fg_w      = (const float*)d_in[10];
    const float* fg_b      = (const float*)d_in[11];
    const float* skip      = (const float*)d_in[12];
    const float* mhn_w     = (const float*)d_in[13];
    const float* w_down    = (const float*)d_in[14];
    const float* post_ln_w = (const float*)d_in[15];
    const float* proj_w    = (const float*)d_in[16];
    const float* proj_b    = (const float*)d_in[17];
    float* out = (float*)d_out;

    float *px, *pup, *plast;
    __nv_bfloat16 *pxh, *pxl, *phh, *phl, *puh, *pul, *pdh, *pdl;
    cudaGetSymbolAddress((void**)&px,    d_x);
    cudaGetSymbolAddress((void**)&pup,   d_up);
    cudaGetSymbolAddress((void**)&plast, d_last);
    cudaGetSymbolAddress((void**)&pxh,   d_xlnhi);
    cudaGetSymbolAddress((void**)&pxl,   d_xlnlo);
    cudaGetSymbolAddress((void**)&phh,   d_hhi);
    cudaGetSymbolAddress((void**)&phl,   d_hlo);
    cudaGetSymbolAddress((void**)&puh,   d_wuphi);
    cudaGetSymbolAddress((void**)&pul,   d_wuplo);
    cudaGetSymbolAddress((void**)&pdh,   d_wdnhi);
    cudaGetSymbolAddress((void**)&pdl,   d_wdnlo);

    static bool attr_set = false;
    if (!attr_set) {
        cudaFuncSetAttribute((const void*)gemm_kernel<0, 128, 128>,
            cudaFuncAttributeMaxDynamicSharedMemorySize, GEMM_SMEM_UP);
        cudaFuncSetAttribute((const void*)gemm_kernel<1, 64, 64>,
            cudaFuncAttributeMaxDynamicSharedMemorySize, GEMM_SMEM_DN);
        cudaFuncSetAttribute((const void*)conv_head_kernel,
            cudaFuncAttributeMaxDynamicSharedMemorySize, CH_SMEM);
        attr_set = true;
    }

    cudaMemcpyAsync(px, in_x, sizeof(float) * (size_t)BS * E,
                    cudaMemcpyDeviceToDevice);

    {
        size_t nu = (size_t)NB * E * 2 * INNER;
        split_kernel<<<(unsigned)(nu / 4 / 256), 256>>>(w_up, puh, pul, nu);
        size_t nd = (size_t)NB * INNER * E;
        split_kernel<<<(unsigned)(nd / 4 / 256), 256>>>(w_down, pdh, pdl, nd);
    }

    for (int bi = 0; bi < NB; bi++) {
        ln_kernel<1><<<BS, 256>>>(px, E, ln_w + (size_t)bi * E,
                                  nullptr, pxh, pxl, E);

        dim3 gu(2 * INNER / 128, BS / 128);
        gemm_kernel<0, 128, 128><<<gu, 256, GEMM_SMEM_UP>>>(pxh, pxl,
                                    puh + (size_t)bi * E * 2 * INNER,
                                    pul + (size_t)bi * E * 2 * INNER,
                                    pup, BS, 2 * INNER, E);

        conv_head_kernel<<<dim3(NHQ / 64, B), 256, CH_SMEM>>>(
            conv_w + (size_t)bi * INNER * CK, conv_b + (size_t)bi * INNER,
            wq + (size_t)bi * NHQ * 16, wk + (size_t)bi * NHQ * 16,
            wv + (size_t)bi * NHQ * 16);

        gate_kernel<<<BS / 8, 256>>>(
            ig_w + (size_t)bi * 3 * INNER * NH, ig_b + (size_t)bi * NH,
            fg_w + (size_t)bi * 3 * INNER * NH, fg_b + (size_t)bi * NH);

        mlstm_kernel<<<dim3((S + TG - 1) / TG, B * NH), 256>>>(
            mhn_w + (size_t)bi * INNER, skip + (size_t)bi * INNER);

        dim3 gd(E / 64, BS / 64);
        gemm_kernel<1, 64, 64><<<gd, 256, GEMM_SMEM_DN>>>(phh, phl,
                                    pdh + (size_t)bi * INNER * E,
                                    pdl + (size_t)bi * INNER * E,
                                    px, BS, E, INNER);
    }

    ln_kernel<0><<<B, 256>>>(px + (size_t)(S - 1) * E, (size_t)S * E,
                             post_ln_w, plast, nullptr, nullptr, E);
    proj_kernel<<<dim3(OUT / 256, B), 256>>>(proj_w, proj_b, out);
}